// round 16
// baseline (speedup 1.0000x reference)
#include <cuda_runtime.h>
#include <cuda_fp16.h>
#include <cstdint>
#include <cstddef>

// ---------------------------------------------------------------------------
// Fused MoE element-wise gating, round 15: round-14 fp16 kernel + unified
// 6-slot x 8KB cp.async staging ring (prefetch depth 3) in the SMEM freed by
// fp16. No cold stages; staging never aliases h1/h2 data. Compute loops,
// epilogues and fold are byte-identical to round 14.
// out[b,o] = sum_e softmax_e(x@Wg+bg) * (L3(L2(L1(x)))+b3)
// B=65536, L=256, E=8, H1=128, H2=64, O=256.
// ---------------------------------------------------------------------------

#define BT 64
#define LDIM 256
#define ODIM 256
#define NE 8
#define H1D 128
#define H2D 64
#define EO 2048
#define OC 128
#define NTHREADS 256

// SMEM byte map
#define XS_B 0              // x tile  [64][256] fp16 swizzled      (32 KB)
#define H1_B 32768          // h1 tile [64][128] fp16               (16 KB)
#define H2_B 49152          // h2 tile [64][64]  fp16               ( 8 KB)
#define ST_B 57344          // staging ring: 6 x 8 KB               (48 KB)
#define SMEM_BYTES 106496

// fp16 paired-k weight images in device scratch (offsets in halfs)
// chunk image: half ((s*N+n)*4+tq)*4+j = W[s*16 + 2tq + (j&1) + 8*(j>>1)][n]
#define W1S_OFF 0        // + e*32768 + c*4096            (c:8, N=128)
#define W2S_OFF 262144   // + e*8192  + c*2048            (c:4, N=64)
#define W3S_OFF 327680   // + e*16384 + nh*8192 + c*4096  (nh:2, c:2, N=128)
#define WGS_OFF 458752   // + e*65536 + nh*32768 + c*4096 (nh:2, c:8, N=128)
#define WS_TOTAL 983040
__device__ __align__(256) __half g_ws[WS_TOTAL];

__device__ __forceinline__ void mma16(float c[4],
                                      uint32_t a0, uint32_t a1, uint32_t a2, uint32_t a3,
                                      uint32_t b0, uint32_t b1) {
    asm volatile(
        "mma.sync.aligned.m16n8k16.row.col.f32.f16.f16.f32 "
        "{%0,%1,%2,%3}, {%4,%5,%6,%7}, {%8,%9}, {%0,%1,%2,%3};"
        : "+f"(c[0]), "+f"(c[1]), "+f"(c[2]), "+f"(c[3])
        : "r"(a0), "r"(a1), "r"(a2), "r"(a3), "r"(b0), "r"(b1));
}

__device__ __forceinline__ float leaky(float v) { return v >= 0.f ? v : 0.01f * v; }

__device__ __forceinline__ void ldsm4(uint32_t a[4], uint32_t addr) {
    asm volatile("ldmatrix.sync.aligned.m8n8.x4.shared.b16 {%0,%1,%2,%3}, [%4];"
                 : "=r"(a[0]), "=r"(a[1]), "=r"(a[2]), "=r"(a[3])
                 : "r"(addr));
}

// volatile + memory clobber — must not be hoisted across CP_WAIT/__syncthreads
__device__ __forceinline__ uint2 lds64(uint32_t addr) {
    uint2 r;
    asm volatile("ld.shared.v2.u32 {%0,%1}, [%2];"
                 : "=r"(r.x), "=r"(r.y) : "r"(addr) : "memory");
    return r;
}

__device__ __forceinline__ void cpa16(uint32_t saddr, const void* g) {
    asm volatile("cp.async.cg.shared.global [%0], [%1], 16;" :: "r"(saddr), "l"(g));
}

__device__ __forceinline__ uint32_t h2u(__half2 h) {
    return *reinterpret_cast<uint32_t*>(&h);
}

// Issue one weight chunk into ring slot (or an empty commit past the end).
// Per-expert chunk order l: 0..7 W1, 8..11 W2 (4KB), 12..19 Wg, 20..21 W3.
__device__ __forceinline__ void issue_chunk(uint32_t sb, int pe, int pl, int slot,
                                            int wgo, int w3o, int tid) {
    if (pe < NE) {
        const __half* src;
        int halfs = 4096;
        if (pl < 8)        src = g_ws + W1S_OFF + pe * 32768 + pl * 4096;
        else if (pl < 12) { src = g_ws + W2S_OFF + pe * 8192 + (pl - 8) * 2048; halfs = 2048; }
        else if (pl < 20)  src = g_ws + WGS_OFF + pe * 65536 + wgo + (pl - 12) * 4096;
        else               src = g_ws + W3S_OFF + pe * 16384 + w3o + (pl - 20) * 4096;
        const uint32_t dst = sb + (uint32_t)ST_B + (uint32_t)(slot << 13);
        for (int i = tid * 8; i < halfs; i += NTHREADS * 8)
            cpa16(dst + (uint32_t)(i * 2), src + i);
    }
    asm volatile("cp.async.commit_group;" ::: "memory");
}

// prefetch cursor advance (issued AFTER the consuming barrier -> WAR-safe)
#define PREFETCH() do { \
    issue_chunk(sb, pe, pl, pslot, wgo, w3o, tid); \
    if (++pl == 22) { pl = 0; ++pe; } \
    if (++pslot == 6) pslot = 0; } while (0)

// wait for the oldest of the 4 pending groups, then block-sync
#define CWAIT_SYNC() do { \
    asm volatile("cp.async.wait_group 3;" ::: "memory"); \
    __syncthreads(); } while (0)

// consume-slot base + advance
#define CBASE(var) \
    const uint32_t var = sb + (uint32_t)ST_B + (uint32_t)(cslot << 13); \
    if (++cslot == 6) cslot = 0

// ---------------------------------------------------------------------------
// Prep: fp16-convert + repack each [32k x N] weight tile into the paired-k
// fp16 image. 256 blocks x 256 threads (identical to round 14).
// ---------------------------------------------------------------------------
__global__ void prep_weights(const float* __restrict__ W1, const float* __restrict__ W2,
                             const float* __restrict__ W3, const float* __restrict__ Wg) {
    __shared__ float t[32][129];
    const int j = blockIdx.x;
    const int tid = threadIdx.x;

    const float* src;
    int stride, N, lg;
    long dst;
    if (j < 64) {                     // W1 [8e][256k][128n]: tile (e, c:8)
        const int e = j >> 3, c = j & 7;
        src = W1 + e * 32768 + c * 32 * 128; stride = 128; N = 128; lg = 7;
        dst = W1S_OFF + e * 32768 + c * 4096;
    } else if (j < 96) {              // W2 [8e][128k][64n]: tile (e, c:4)
        const int t2 = j - 64, e = t2 >> 2, c = t2 & 3;
        src = W2 + e * 8192 + c * 32 * 64; stride = 64; N = 64; lg = 6;
        dst = W2S_OFF + e * 8192 + c * 2048;
    } else if (j < 128) {             // W3 [8e][64k][256n]: tile (e, nh:2, c:2)
        const int t3 = j - 96, e = t3 >> 2, nh = (t3 >> 1) & 1, c = t3 & 1;
        src = W3 + e * 16384 + c * 32 * 256 + nh * 128; stride = 256; N = 128; lg = 7;
        dst = W3S_OFF + e * 16384 + nh * 8192 + c * 4096;
    } else {                          // Wg [256k][2048n]: tile (e, nh:2, c:8)
        const int t4 = j - 128, e = t4 >> 4, nh = (t4 >> 3) & 1, c = t4 & 7;
        src = Wg + c * 32 * EO + e * 256 + nh * 128; stride = EO; N = 128; lg = 7;
        dst = WGS_OFF + e * 65536 + nh * 32768 + c * 4096;
    }

    for (int i = tid; i < 32 * N; i += 256) {
        const int k = i >> lg, n = i & (N - 1);
        t[k][n] = src[(size_t)k * stride + n];
    }
    __syncthreads();
    for (int idx = tid; idx < 32 * N; idx += 256) {
        const int jj = idx & 3;
        const int tq = (idx >> 2) & 3;
        const int n  = (idx >> 4) & (N - 1);
        const int s  = idx >> (4 + lg);
        const int k  = s * 16 + 2 * tq + (jj & 1) + ((jj >> 1) << 3);
        g_ws[dst + idx] = __float2half_rn(t[k][n]);
    }
}

__global__ void __launch_bounds__(NTHREADS, 2)
moe_fused_kernel(const float* __restrict__ x,
                 const float* __restrict__ b1, const float* __restrict__ b2,
                 const float* __restrict__ b3, const float* __restrict__ bg,
                 float* __restrict__ out) {
    extern __shared__ float sm[];
    char* smc = reinterpret_cast<char*>(sm);
    const uint32_t sb = (uint32_t)__cvta_generic_to_shared(sm);

    const int tid  = threadIdx.x;
    const int w    = tid >> 5;
    const int lane = tid & 31;
    const int g    = lane >> 2;    // 0..7
    const int tq   = lane & 3;     // 0..3
    const int mq   = w & 1;        // m-warp: rows mq*32 .. +31
    const int ng   = w >> 1;       // n-group (0..3): 32 cols

    const int btile = blockIdx.x >> 1;
    const int octa  = (blockIdx.x & 1) * OC;
    const int row0  = btile * BT;
    const int wgo   = octa ? 32768 : 0;   // Wg image half-offset
    const int w3o   = octa ? 8192 : 0;    // W3 image half-offset

    // ldmatrix per-lane addressing (fp16 rows; 16B granules, gran ^ (row&7))
    const int lbase = (((lane >> 3) & 1) << 3) + (lane & 7);
    const int lrow0 = mq * 32 + lbase;
    const int lrow1 = lrow0 + 16;               // same low 3 bits
    const int rm    = lrow0 & 7;
    const int hi    = lane >> 4;                // 0/1: k-halves of the tile
    const uint32_t xRow0  = sb + XS_B + (uint32_t)(lrow0 * 512);
    const uint32_t xRow1  = sb + XS_B + (uint32_t)(lrow1 * 512);
    const uint32_t h1Row0 = sb + H1_B + (uint32_t)(lrow0 * 256);
    const uint32_t h1Row1 = sb + H1_B + (uint32_t)(lrow1 * 256);
    const uint32_t h2Row0 = sb + H2_B + (uint32_t)(lrow0 * 128);
    const uint32_t h2Row1 = sb + H2_B + (uint32_t)(lrow1 * 128);

    // B fragment byte offsets inside a chunk image: n*32 + tq*8
    const int nb1 = ng * 32 + g;
    const int nb2 = ng * 16 + g;
    const uint32_t boffB  = (uint32_t)(nb1 * 32 + tq * 8);
    const uint32_t boffB2 = (uint32_t)(nb2 * 32 + tq * 8);

    // ---- load x tile -> fp16 -> swizzled SMEM (16B granules) ----
    for (int i = tid; i < BT * 32; i += NTHREADS) {
        const int r = i >> 5, gr = i & 31;
        const float4* xr = reinterpret_cast<const float4*>(x + (size_t)(row0 + r) * LDIM);
        const float4 a = xr[gr * 2];
        const float4 b = xr[gr * 2 + 1];
        uint4 u;
        u.x = h2u(__floats2half2_rn(a.x, a.y));
        u.y = h2u(__floats2half2_rn(a.z, a.w));
        u.z = h2u(__floats2half2_rn(b.x, b.y));
        u.w = h2u(__floats2half2_rn(b.z, b.w));
        *reinterpret_cast<uint4*>(smc + XS_B + r * 512 + ((gr ^ (r & 7)) << 4)) = u;
    }

    float acc[8][4], ssum[8][4];
#pragma unroll
    for (int i = 0; i < 8; i++)
#pragma unroll
        for (int jj = 0; jj < 4; jj++) { acc[i][jj] = 0.f; ssum[i][jj] = 0.f; }

    // staging ring cursors + prologue: 4 groups in flight
    int pe = 0, pl = 0, pslot = 0, cslot = 0;
    PREFETCH(); PREFETCH(); PREFETCH(); PREFETCH();

    for (int e = 0; e < NE; e++) {
        // ================= layer 1: h1 = leaky(x @ W1_e + b1_e) ================
        float c1[2][4][4];
#pragma unroll
        for (int t = 0; t < 2; t++)
#pragma unroll
            for (int i = 0; i < 4; i++)
#pragma unroll
                for (int jj = 0; jj < 4; jj++) c1[t][i][jj] = 0.f;

        for (int c = 0; c < 8; c++) {
            CWAIT_SYNC();
            PREFETCH();
            CBASE(wbuf);
            const uint32_t wb1 = wbuf + boffB;
#pragma unroll
            for (int s = 0; s < 2; s++) {
                const uint32_t sw = (uint32_t)((((c << 2) + (s << 1) + hi) ^ rm) << 4);
                uint32_t a0[4], a1[4];
                ldsm4(a0, xRow0 + sw);
                ldsm4(a1, xRow1 + sw);
                uint2 bp[4];
#pragma unroll
                for (int nt = 0; nt < 4; nt++)
                    bp[nt] = lds64(wb1 + (uint32_t)(s * 4096 + nt * 256));
#pragma unroll
                for (int nt = 0; nt < 4; nt++) {
                    mma16(c1[0][nt], a0[0], a0[1], a0[2], a0[3], bp[nt].x, bp[nt].y);
                    mma16(c1[1][nt], a1[0], a1[1], a1[2], a1[3], bp[nt].x, bp[nt].y);
                }
            }
        }

        // h1 epilogue: bias + leaky -> fp16 -> h1 region (ordered before L2's
        // first ldsm by the L2 loop's first CWAIT_SYNC barrier)
        {
#pragma unroll
            for (int t = 0; t < 2; t++) {
                const int ar = mq * 32 + t * 16 + g;
                const int arm = ar & 7;
#pragma unroll
                for (int nt = 0; nt < 4; nt++) {
                    const int colb = ng * 32 + nt * 8 + 2 * tq;
                    const float bb0 = b1[e * H1D + colb];
                    const float bb1 = b1[e * H1D + colb + 1];
                    const int gr = colb >> 3;
                    const int bo = (colb & 7) * 2;
                    *reinterpret_cast<__half2*>(smc + H1_B + ar * 256 +
                        ((gr ^ arm) << 4) + bo) =
                        __floats2half2_rn(leaky(c1[t][nt][0] + bb0), leaky(c1[t][nt][1] + bb1));
                    *reinterpret_cast<__half2*>(smc + H1_B + (ar + 8) * 256 +
                        ((gr ^ arm) << 4) + bo) =
                        __floats2half2_rn(leaky(c1[t][nt][2] + bb0), leaky(c1[t][nt][3] + bb1));
                }
            }
        }

        // ================= layer 2: h2 = leaky(h1 @ W2_e + b2_e) ===============
        float c2[2][2][4];
#pragma unroll
        for (int t = 0; t < 2; t++)
#pragma unroll
            for (int i = 0; i < 2; i++)
#pragma unroll
                for (int jj = 0; jj < 4; jj++) c2[t][i][jj] = 0.f;

        for (int c = 0; c < 4; c++) {
            CWAIT_SYNC();
            PREFETCH();
            CBASE(wbuf);
            const uint32_t wb2 = wbuf + boffB2;
#pragma unroll
            for (int s = 0; s < 2; s++) {
                const uint32_t sw = (uint32_t)((((c << 2) + (s << 1) + hi) ^ rm) << 4);
                uint32_t a0[4], a1[4];
                ldsm4(a0, h1Row0 + sw);
                ldsm4(a1, h1Row1 + sw);
                uint2 bp[2];
#pragma unroll
                for (int nt = 0; nt < 2; nt++)
                    bp[nt] = lds64(wb2 + (uint32_t)(s * 2048 + nt * 256));
#pragma unroll
                for (int nt = 0; nt < 2; nt++) {
                    mma16(c2[0][nt], a0[0], a0[1], a0[2], a0[3], bp[nt].x, bp[nt].y);
                    mma16(c2[1][nt], a1[0], a1[1], a1[2], a1[3], bp[nt].x, bp[nt].y);
                }
            }
        }

        // h2 epilogue -> h2 region (ordered before L3 reads by gate-loop syncs)
        {
#pragma unroll
            for (int t = 0; t < 2; t++) {
                const int ar = mq * 32 + t * 16 + g;
                const int arm = ar & 7;
#pragma unroll
                for (int nt = 0; nt < 2; nt++) {
                    const int colb = ng * 16 + nt * 8 + 2 * tq;
                    const float bb0 = b2[e * H2D + colb];
                    const float bb1 = b2[e * H2D + colb + 1];
                    const int gr = colb >> 3;
                    const int bo = (colb & 7) * 2;
                    *reinterpret_cast<__half2*>(smc + H2_B + ar * 128 +
                        ((gr ^ arm) << 4) + bo) =
                        __floats2half2_rn(leaky(c2[t][nt][0] + bb0), leaky(c2[t][nt][1] + bb1));
                    *reinterpret_cast<__half2*>(smc + H2_B + (ar + 8) * 128 +
                        ((gr ^ arm) << 4) + bo) =
                        __floats2half2_rn(leaky(c2[t][nt][2] + bb0), leaky(c2[t][nt][3] + bb1));
                }
            }
        }

        // ====== gate GEMM ======================================================
        float cg[2][4][4];
#pragma unroll
        for (int t = 0; t < 2; t++)
#pragma unroll
            for (int i = 0; i < 4; i++)
#pragma unroll
                for (int jj = 0; jj < 4; jj++) cg[t][i][jj] = 0.f;

        for (int c = 0; c < 8; c++) {
            CWAIT_SYNC();
            PREFETCH();
            CBASE(wbuf);
            const uint32_t wbg = wbuf + boffB;
#pragma unroll
            for (int s = 0; s < 2; s++) {
                const uint32_t sw = (uint32_t)((((c << 2) + (s << 1) + hi) ^ rm) << 4);
                uint32_t a0[4], a1[4];
                ldsm4(a0, xRow0 + sw);
                ldsm4(a1, xRow1 + sw);
                uint2 bp[4];
#pragma unroll
                for (int nt = 0; nt < 4; nt++)
                    bp[nt] = lds64(wbg + (uint32_t)(s * 4096 + nt * 256));
#pragma unroll
                for (int nt = 0; nt < 4; nt++) {
                    mma16(cg[0][nt], a0[0], a0[1], a0[2], a0[3], bp[nt].x, bp[nt].y);
                    mma16(cg[1][nt], a1[0], a1[1], a1[2], a1[3], bp[nt].x, bp[nt].y);
                }
            }
        }

        // ====== layer 3: consume both W3 chunks, then per-m-tile compute+fold ==
        CWAIT_SYNC();
        PREFETCH();
        CBASE(w3buf0);
        CWAIT_SYNC();
        PREFETCH();
        CBASE(w3buf1);
        const uint32_t w3a = w3buf0 + boffB;
        const uint32_t w3b = w3buf1 + boffB;

#pragma unroll 1
        for (int t = 0; t < 2; t++) {
            float co[4][4];
#pragma unroll
            for (int i = 0; i < 4; i++)
#pragma unroll
                for (int jj = 0; jj < 4; jj++) co[i][jj] = 0.f;

            const uint32_t hRow = t ? h2Row1 : h2Row0;
#pragma unroll
            for (int ks = 0; ks < 4; ks++) {
                const uint32_t sw = (uint32_t)((((ks << 1) + hi) ^ rm) << 4);
                uint32_t a[4];
                ldsm4(a, hRow + sw);
                const uint32_t wb3 = (ks < 2) ? w3a : w3b;
                const int s3 = ks & 1;
                uint2 bp[4];
#pragma unroll
                for (int nt = 0; nt < 4; nt++)
                    bp[nt] = lds64(wb3 + (uint32_t)(s3 * 4096 + nt * 256));
#pragma unroll
                for (int nt = 0; nt < 4; nt++)
                    mma16(co[nt], a[0], a[1], a[2], a[3], bp[nt].x, bp[nt].y);
            }
            // fold: acc += exp(gate)*(o+b3); ssum += exp(gate)
#pragma unroll
            for (int nt = 0; nt < 4; nt++) {
                const int colc = octa + ng * 32 + nt * 8 + 2 * tq;
                const float bg0 = bg[e * ODIM + colc];
                const float bg1 = bg[e * ODIM + colc + 1];
                const float b30 = b3[e * ODIM + colc];
                const float b31 = b3[e * ODIM + colc + 1];
                const int ai = t * 4 + nt;
                float p;
                p = __expf(cg[t][nt][0] + bg0); acc[ai][0] += p * (co[nt][0] + b30); ssum[ai][0] += p;
                p = __expf(cg[t][nt][1] + bg1); acc[ai][1] += p * (co[nt][1] + b31); ssum[ai][1] += p;
                p = __expf(cg[t][nt][2] + bg0); acc[ai][2] += p * (co[nt][2] + b30); ssum[ai][2] += p;
                p = __expf(cg[t][nt][3] + bg1); acc[ai][3] += p * (co[nt][3] + b31); ssum[ai][3] += p;
            }
        }
        // next expert's first CWAIT_SYNC barrier fences h1/h2/ring reuse
    }

    // ---- epilogue: out = acc / ssum ----
#pragma unroll
    for (int ai = 0; ai < 8; ai++) {
        const int t = ai >> 2, nt = ai & 3;
        const int colc = octa + ng * 32 + nt * 8 + 2 * tq;
        const int ar = mq * 32 + t * 16 + g;
        const size_t r0 = (size_t)(row0 + ar) * ODIM;
        const size_t r1 = (size_t)(row0 + ar + 8) * ODIM;
        float2 v0 = make_float2(acc[ai][0] / ssum[ai][0], acc[ai][1] / ssum[ai][1]);
        float2 v1 = make_float2(acc[ai][2] / ssum[ai][2], acc[ai][3] / ssum[ai][3]);
        *reinterpret_cast<float2*>(out + r0 + colc) = v0;
        *reinterpret_cast<float2*>(out + r1 + colc) = v1;
    }
}

extern "C" void kernel_launch(void* const* d_in, const int* in_sizes, int n_in,
                              void* d_out, int out_size) {
    const float* x  = (const float*)d_in[0];
    const float* W1 = (const float*)d_in[1];
    const float* b1 = (const float*)d_in[2];
    const float* W2 = (const float*)d_in[3];
    const float* b2 = (const float*)d_in[4];
    const float* W3 = (const float*)d_in[5];
    const float* b3 = (const float*)d_in[6];
    const float* Wg = (const float*)d_in[7];
    const float* bg = (const float*)d_in[8];
    float* out = (float*)d_out;
    (void)n_in; (void)out_size;

    const int B  = in_sizes[0] / LDIM;       // 65536
    const int nb = (B / BT) * 2;             // 2048 CTAs

    prep_weights<<<256, 256>>>(W1, W2, W3, Wg);

    cudaFuncSetAttribute(moe_fused_kernel,
                         cudaFuncAttributeMaxDynamicSharedMemorySize, SMEM_BYTES);
    moe_fused_kernel<<<nb, NTHREADS, SMEM_BYTES>>>(x, b1, b2, b3, bg, out);
}